// round 14
// baseline (speedup 1.0000x reference)
#include <cuda_runtime.h>
#include <cuda_fp16.h>
#include <stdint.h>

#define IN_F   2048
#define OUT_F  2048
#define TOPK   1024
#define M_FIX  16384

#define BM 128
#define BN 128
#define BK 64
#define NSTAGES 3
#define NT (IN_F / BK)              // 32
#define STAGE_BYTES 16384           // B only (A goes register-direct)
#define DSMEM (NSTAGES * STAGE_BYTES + 1024)
#define KCHUNKS (IN_F / 16)         // 128 k16-chunks per row
#define NFRAG ((M_FIX / 16) * KCHUNKS)   // 131072 fragments

// Scratch: masked W (fp16, [out][in]) and FRAGMENT-PERMUTED fp16 activations.
// g_ahp layout: fragment F = mb*KCHUNKS + kc (mb = m/16, kc = k/16);
// 512B per fragment; lane l's 16B at F*256h + l*8h holds the 4 mma A-regs:
//   h0h1=A[g][2t,2t+1] h2h3=A[g+8][2t,2t+1] h4h5=A[g][2t+8,2t+9] h6h7=A[g+8][2t+8,2t+9]
__device__ __half g_wh [(size_t)OUT_F * IN_F];
__device__ __half g_ahp[(size_t)M_FIX * IN_F];

__device__ __forceinline__ uint32_t smem_u32(const void* p) {
    return (uint32_t)__cvta_generic_to_shared(p);
}
__device__ __forceinline__ void cp16cg(uint32_t dst, const void* src) {
    asm volatile("cp.async.cg.shared.global [%0], [%1], 16;\n" :: "r"(dst), "l"(src));
}
__device__ __forceinline__ void ldm_x4(uint32_t (&r)[4], uint32_t addr) {
    asm volatile("ldmatrix.sync.aligned.m8n8.x4.shared.b16 {%0,%1,%2,%3}, [%4];"
                 : "=r"(r[0]), "=r"(r[1]), "=r"(r[2]), "=r"(r[3]) : "r"(addr));
}
__device__ __forceinline__ void mma_f16_v(float c[4], const uint4 a, const uint32_t b[2]) {
    asm volatile(
        "mma.sync.aligned.m16n8k16.row.col.f32.f16.f16.f32 "
        "{%0,%1,%2,%3}, {%4,%5,%6,%7}, {%8,%9}, {%0,%1,%2,%3};\n"
        : "+f"(c[0]), "+f"(c[1]), "+f"(c[2]), "+f"(c[3])
        : "r"(a.x), "r"(a.y), "r"(a.z), "r"(a.w), "r"(b[0]), "r"(b[1]));
}

// ---------------------------------------------------------------------------
// Kernel 1 (fused prep, parity-interleaved):
//   even blocks: per-row exact top-k mask (radix select on |w| bits, ties
//     lowest-index-first per jax.lax.top_k), row = blockIdx.x/2 -> g_wh fp16.
//   odd blocks:  build 64 fragment-permuted A fragments (fp16) into g_ahp.
// ---------------------------------------------------------------------------
__global__ void prep_kernel(const float* __restrict__ W,
                            const float* __restrict__ x) {
    __shared__ unsigned s_bits[IN_F];
    __shared__ int s_hist[256];
    __shared__ int s_suf[256];
    __shared__ int s_tmp[16];
    __shared__ int s_sel[2];

    const int tid  = threadIdx.x;
    const int lane = tid & 31;
    const int warp = tid >> 5;

    if (blockIdx.x & 1) {
        // ---- A-permute job: 64 fragments per block, 8 per warp ----
        const int Fbase = (blockIdx.x >> 1) * 64;
        const int g = lane >> 2;
        const int t = lane & 3;
        #pragma unroll
        for (int i = 0; i < 8; ++i) {
            const int F  = Fbase + warp * 8 + i;
            const int mb = F >> 7;          // / KCHUNKS
            const int kc = F & 127;
            const float* p0 = x + (size_t)(mb * 16 + g) * IN_F + kc * 16 + 2 * t;
            const float* p1 = p0 + 8 * IN_F;
            float2 v0 = *reinterpret_cast<const float2*>(p0);
            float2 v1 = *reinterpret_cast<const float2*>(p1);
            float2 v2 = *reinterpret_cast<const float2*>(p0 + 8);
            float2 v3 = *reinterpret_cast<const float2*>(p1 + 8);
            __half2 h0 = __floats2half2_rn(v0.x, v0.y);
            __half2 h1 = __floats2half2_rn(v1.x, v1.y);
            __half2 h2 = __floats2half2_rn(v2.x, v2.y);
            __half2 h3 = __floats2half2_rn(v3.x, v3.y);
            uint4 o;
            o.x = *reinterpret_cast<uint32_t*>(&h0);
            o.y = *reinterpret_cast<uint32_t*>(&h1);
            o.z = *reinterpret_cast<uint32_t*>(&h2);
            o.w = *reinterpret_cast<uint32_t*>(&h3);
            *reinterpret_cast<uint4*>(g_ahp + (size_t)F * 256 + lane * 8) = o;
        }
        return;
    }

    // ---- mask job ----
    const int row = blockIdx.x >> 1;
    const float* wrow = W + (size_t)row * IN_F;

    #pragma unroll
    for (int i = 0; i < IN_F / 1024; ++i) {
        const int c4 = i * 256 + tid;
        float4 v = reinterpret_cast<const float4*>(wrow)[c4];
        s_bits[c4 * 4 + 0] = __float_as_uint(v.x) & 0x7fffffffu;
        s_bits[c4 * 4 + 1] = __float_as_uint(v.y) & 0x7fffffffu;
        s_bits[c4 * 4 + 2] = __float_as_uint(v.z) & 0x7fffffffu;
        s_bits[c4 * 4 + 3] = __float_as_uint(v.w) & 0x7fffffffu;
    }
    __syncthreads();

    unsigned prefix = 0;
    int k = TOPK;
    #pragma unroll
    for (int pass = 0; pass < 4; ++pass) {
        const int shift = 24 - 8 * pass;
        s_hist[tid] = 0;
        __syncthreads();
        const unsigned pm = (pass == 0) ? 0u : (0xffffffffu << (shift + 8));
        #pragma unroll
        for (int i = 0; i < IN_F / 256; ++i) {
            unsigned b = s_bits[i * 256 + tid];
            if ((b & pm) == prefix)
                atomicAdd(&s_hist[(b >> shift) & 0xffu], 1);
        }
        __syncthreads();
        int v = s_hist[tid];
        #pragma unroll
        for (int off = 1; off < 32; off <<= 1) {
            int t2 = __shfl_down_sync(0xffffffffu, v, off);
            if (lane + off < 32) v += t2;
        }
        if (lane == 0) s_tmp[warp] = v;
        __syncthreads();
        if (tid < 8) {
            int w = s_tmp[tid];
            #pragma unroll
            for (int off = 1; off < 8; off <<= 1) {
                int t2 = __shfl_down_sync(0xffu, w, off, 8);
                if (tid + off < 8) w += t2;
            }
            s_tmp[8 + tid] = w;
        }
        __syncthreads();
        const int vincl = v + ((warp < 7) ? s_tmp[8 + warp + 1] : 0);
        s_suf[tid] = vincl;
        __syncthreads();
        const int suf1 = (tid < 255) ? s_suf[tid + 1] : 0;
        if (vincl >= k && suf1 < k) {
            s_sel[0] = tid;
            s_sel[1] = k - suf1;
        }
        __syncthreads();
        prefix |= ((unsigned)s_sel[0]) << shift;
        k = s_sel[1];
        __syncthreads();
    }
    const unsigned t = prefix;
    const int kfin = k;

    const int CH = IN_F / 256;
    const int base = tid * CH;
    int cnt = 0;
    #pragma unroll
    for (int j = 0; j < CH; ++j)
        if (s_bits[base + j] == t) cnt++;
    int v2 = cnt;
    #pragma unroll
    for (int off = 1; off < 32; off <<= 1) {
        int tt = __shfl_up_sync(0xffffffffu, v2, off);
        if (lane >= off) v2 += tt;
    }
    if (lane == 31) s_tmp[warp] = v2;
    __syncthreads();
    if (tid < 8) {
        int w = s_tmp[tid];
        #pragma unroll
        for (int off = 1; off < 8; off <<= 1) {
            int tt = __shfl_up_sync(0xffu, w, off, 8);
            if (tid >= off) w += tt;
        }
        s_tmp[8 + tid] = w;
    }
    __syncthreads();
    int eq_before = v2 - cnt + ((warp > 0) ? s_tmp[8 + warp - 1] : 0);

    #pragma unroll
    for (int j = 0; j < CH; ++j) {
        const int c = base + j;
        const unsigned b = s_bits[c];
        float v = 0.0f;
        if (b > t) {
            v = wrow[c];
        } else if (b == t) {
            if (eq_before < kfin) v = wrow[c];
            eq_before++;
        }
        g_wh[(size_t)row * IN_F + c] = __float2half_rn(v);
    }
}

// ---------------------------------------------------------------------------
// Kernel 2: fp16 mma.sync GEMM, A register-direct.
// A fragments: one LDG.128 per fragment from g_ahp (L1-cached, 4x reuse
// across wn-warps) — NO smem staging for A. B: cp.async + ldmatrix as in
// the proven r9 kernel. Crossbar load drops 128 -> 48 B/cyc.
// 128x128 tile, BK=64, 256 threads, 2x4 warps, 64x32 warp tiles, 2 CTAs/SM.
// ---------------------------------------------------------------------------
__global__ __launch_bounds__(256, 2)
void gemm_kernel(const float* __restrict__ bias, float* __restrict__ C) {
    extern __shared__ char dsm[];
    __shared__ float s_bias[BN];

    const int tid  = threadIdx.x;
    const int lane = tid & 31;
    const int wid  = tid >> 5;
    const int wm   = wid >> 2;           // 0..1  (64 rows each)
    const int wn   = wid & 3;            // 0..3  (32 cols each)
    const int m0 = blockIdx.y * BM;
    const int n0 = blockIdx.x * BN;

    const uint32_t base = (smem_u32(dsm) + 1023) & ~1023u;
    if (tid < BN) s_bias[tid] = bias[n0 + tid];

    const int brow = (lane & 7) + ((lane >> 4) << 3);
    const int bsel = (lane >> 3) & 1;
    const uint32_t lxor_b = (uint32_t)((lane & 7) << 4);

    // A fragment base: fragment (mb, kc) at g_ahp + (mb*128+kc)*256 halves.
    const int mb0 = (m0 >> 4) + wm * 4;          // + mt
    const __half* aptr = g_ahp + (size_t)mb0 * (KCHUNKS * 256) + lane * 8;

    auto issue = [&](int kt, int st) {           // B only: 128 rows x 128B
        const uint32_t sb = base + st * STAGE_BYTES;
        const int k0 = kt * BK;
        #pragma unroll
        for (int i = 0; i < 4; ++i) {
            const int id = i * 256 + tid;
            const int n = id >> 3, j = id & 7;
            cp16cg(sb + n * 128 + (((uint32_t)(j << 4)) ^ ((uint32_t)((n & 7) << 4))),
                   g_wh + (size_t)(n0 + n) * IN_F + k0 + j * 8);
        }
        asm volatile("cp.async.commit_group;\n" ::);
    };

    float acc[4][4][4] = {};

    issue(0, 0);
    issue(1, 1);

    int st = 0;
    for (int kt = 0; kt < NT; ++kt) {
        if (kt < NT - 2)
            asm volatile("cp.async.wait_group 1;\n" ::);
        else
            asm volatile("cp.async.wait_group 0;\n" ::);
        __syncthreads();

        if (kt + 2 < NT) {
            int st2 = st + 2;
            if (st2 >= NSTAGES) st2 -= NSTAGES;
            issue(kt + 2, st2);
        }

        const uint32_t sb = base + st * STAGE_BYTES;

        #pragma unroll
        for (int kk = 0; kk < 4; ++kk) {         // 4 k16 chunks in BK=64
            const int kc = kt * 4 + kk;
            uint4 a[4];
            #pragma unroll
            for (int mt = 0; mt < 4; ++mt)
                a[mt] = *reinterpret_cast<const uint4*>(
                    aptr + ((size_t)mt * KCHUNKS + kc) * 256);
            const uint32_t csel_b = (((uint32_t)((kk * 2 + bsel) << 4)) ^ lxor_b);
            uint32_t b[4][2];
            #pragma unroll
            for (int np = 0; np < 2; ++np) {
                uint32_t r[4];
                ldm_x4(r, sb + (uint32_t)((wn * 32 + np * 16 + brow) * 128) + csel_b);
                b[2 * np][0] = r[0]; b[2 * np][1] = r[1];
                b[2 * np + 1][0] = r[2]; b[2 * np + 1][1] = r[3];
            }
            #pragma unroll
            for (int mt = 0; mt < 4; ++mt)
                #pragma unroll
                for (int nt = 0; nt < 4; ++nt)
                    mma_f16_v(acc[mt][nt], a[mt], b[nt]);
        }
        ++st;
        if (st == NSTAGES) st = 0;
    }

    // Epilogue: bias add, float2 stores.
    const int g = lane >> 2;
    const int t = lane & 3;
    #pragma unroll
    for (int mt = 0; mt < 4; ++mt) {
        const int r0 = m0 + wm * 64 + mt * 16 + g;
        #pragma unroll
        for (int nt = 0; nt < 4; ++nt) {
            const int cl = wn * 32 + nt * 8 + t * 2;   // local col in [0,128)
            const float bx = s_bias[cl], by = s_bias[cl + 1];
            float2 o0, o1;
            o0.x = acc[mt][nt][0] + bx;
            o0.y = acc[mt][nt][1] + by;
            o1.x = acc[mt][nt][2] + bx;
            o1.y = acc[mt][nt][3] + by;
            *reinterpret_cast<float2*>(C + (size_t)r0 * OUT_F + n0 + cl) = o0;
            *reinterpret_cast<float2*>(C + (size_t)(r0 + 8) * OUT_F + n0 + cl) = o1;
        }
    }
}

// ---------------------------------------------------------------------------
extern "C" void kernel_launch(void* const* d_in, const int* in_sizes, int n_in,
                              void* d_out, int out_size) {
    const float* x    = (const float*)d_in[0];   // [M, 2048]
    const float* W    = (const float*)d_in[1];   // [2048, 2048]
    const float* bias = (const float*)d_in[2];   // [2048]
    float* out = (float*)d_out;

    const int M = in_sizes[0] / IN_F;            // 16384

    cudaFuncSetAttribute(gemm_kernel,
                         cudaFuncAttributeMaxDynamicSharedMemorySize, DSMEM);

    // Fused prep, parity-interleaved: 2048 mask + 2048 A-permute blocks.
    prep_kernel<<<2 * OUT_F, 256>>>(W, x);

    dim3 grid(OUT_F / BN, M / BM);               // (16, 128)
    gemm_kernel<<<grid, 256, DSMEM>>>(bias, out);
}

// round 15
// speedup vs baseline: 1.2623x; 1.2623x over previous
#include <cuda_runtime.h>
#include <cuda_fp16.h>
#include <stdint.h>

#define IN_F   2048
#define OUT_F  2048
#define TOPK   1024
#define M_FIX  16384

#define BM 128
#define BN 128
#define BK 64
#define NSTAGES 3
#define NT (IN_F / BK)              // 32
#define STAGE_BYTES 32768           // A 16KB + B 16KB (fp16)
#define B_OFF 16384
#define DSMEM (NSTAGES * STAGE_BYTES + 1024)

#define NPREP (2 * OUT_F)           // 4096 prep blocks (parity-interleaved)
#define N_NTILE (OUT_F / BN)        // 16
#define N_MTILE (M_FIX / BM)        // 128

// Scratch: masked W (fp16, [out][in]) and fp16 activations.
__device__ __half g_wh[(size_t)OUT_F * IN_F];
__device__ __half g_ah[(size_t)M_FIX * IN_F];
// Dependency counters: mask rows done per n-tile, cvt slices done per m-tile.
__device__ int g_mask_done[N_NTILE];
__device__ int g_a_done[N_MTILE];

__device__ __forceinline__ uint32_t smem_u32(const void* p) {
    return (uint32_t)__cvta_generic_to_shared(p);
}
__device__ __forceinline__ void cp16cg(uint32_t dst, const void* src) {
    asm volatile("cp.async.cg.shared.global [%0], [%1], 16;\n" :: "r"(dst), "l"(src));
}
__device__ __forceinline__ void ldm_x4(uint32_t (&r)[4], uint32_t addr) {
    asm volatile("ldmatrix.sync.aligned.m8n8.x4.shared.b16 {%0,%1,%2,%3}, [%4];"
                 : "=r"(r[0]), "=r"(r[1]), "=r"(r[2]), "=r"(r[3]) : "r"(addr));
}
__device__ __forceinline__ void mma_f16(float c[4], const uint32_t a[4], const uint32_t b[2]) {
    asm volatile(
        "mma.sync.aligned.m16n8k16.row.col.f32.f16.f16.f32 "
        "{%0,%1,%2,%3}, {%4,%5,%6,%7}, {%8,%9}, {%0,%1,%2,%3};\n"
        : "+f"(c[0]), "+f"(c[1]), "+f"(c[2]), "+f"(c[3])
        : "r"(a[0]), "r"(a[1]), "r"(a[2]), "r"(a[3]), "r"(b[0]), "r"(b[1]));
}

// ---------------------------------------------------------------------------
// Kernel 0: reset dependency counters (graph-capturable, deterministic).
// ---------------------------------------------------------------------------
__global__ void reset_kernel() {
    const int i = threadIdx.x;
    if (i < N_NTILE) g_mask_done[i] = 0;
    if (i < N_MTILE) g_a_done[i] = 0;
}

// ---------------------------------------------------------------------------
// Kernel 1 (FUSED prep + GEMM, flag-synchronized):
//   blocks [0, 4096), even:  mask row blockIdx/2 (radix top-k select, ties
//     lowest-index-first per jax.lax.top_k) -> g_wh fp16; ++g_mask_done.
//   blocks [0, 4096), odd:   cvt x slice blockIdx/2 (8 rows) -> g_ah fp16;
//     ++g_a_done.
//   blocks [4096, 6144): GEMM tile; spins until its 128 W rows and 128 x
//     rows are ready, then runs the proven r13 pipeline.
// Work distributor dispatches in index order -> all prep blocks dispatched
// before any GEMM block -> no deadlock. Prep (LSU/ALU) overlaps GEMM (tensor).
// ---------------------------------------------------------------------------
__global__ __launch_bounds__(256, 2)
void fused_kernel(const float* __restrict__ W, const float4* __restrict__ x,
                  const float* __restrict__ bias, float* __restrict__ C) {
    extern __shared__ char dsm[];
    __shared__ unsigned s_bits[IN_F];
    __shared__ int s_hist[256];
    __shared__ int s_suf[256];
    __shared__ int s_tmp[16];
    __shared__ int s_sel[2];

    const int tid  = threadIdx.x;
    const int lane = tid & 31;
    const int warp = tid >> 5;

    if (blockIdx.x < NPREP) {
        if (blockIdx.x & 1) {
            // ---- cvt job: 4096 float4 (8 x-rows) per block ----
            const int slice = blockIdx.x >> 1;
            const size_t base4 = (size_t)slice * 4096;
            #pragma unroll
            for (int j = 0; j < 8; ++j) {
                const size_t i4 = base4 + (size_t)j * 512 + tid * 2;
                float4 v0 = x[i4];
                float4 v1 = x[i4 + 1];
                __half2 h0 = __floats2half2_rn(v0.x, v0.y);
                __half2 h1 = __floats2half2_rn(v0.z, v0.w);
                __half2 h2 = __floats2half2_rn(v1.x, v1.y);
                __half2 h3 = __floats2half2_rn(v1.z, v1.w);
                uint4 o;
                o.x = *reinterpret_cast<uint32_t*>(&h0);
                o.y = *reinterpret_cast<uint32_t*>(&h1);
                o.z = *reinterpret_cast<uint32_t*>(&h2);
                o.w = *reinterpret_cast<uint32_t*>(&h3);
                *reinterpret_cast<uint4*>(g_ah + i4 * 4) = o;
            }
            __threadfence();
            __syncthreads();
            if (tid == 0) atomicAdd(&g_a_done[slice >> 4], 1);
            return;
        }

        // ---- mask job ----
        const int row = blockIdx.x >> 1;
        const float* wrow = W + (size_t)row * IN_F;

        #pragma unroll
        for (int i = 0; i < IN_F / 1024; ++i) {
            const int c4 = i * 256 + tid;
            float4 v = reinterpret_cast<const float4*>(wrow)[c4];
            s_bits[c4 * 4 + 0] = __float_as_uint(v.x) & 0x7fffffffu;
            s_bits[c4 * 4 + 1] = __float_as_uint(v.y) & 0x7fffffffu;
            s_bits[c4 * 4 + 2] = __float_as_uint(v.z) & 0x7fffffffu;
            s_bits[c4 * 4 + 3] = __float_as_uint(v.w) & 0x7fffffffu;
        }
        __syncthreads();

        unsigned prefix = 0;
        int k = TOPK;
        #pragma unroll
        for (int pass = 0; pass < 4; ++pass) {
            const int shift = 24 - 8 * pass;
            s_hist[tid] = 0;
            __syncthreads();
            const unsigned pm = (pass == 0) ? 0u : (0xffffffffu << (shift + 8));
            #pragma unroll
            for (int i = 0; i < IN_F / 256; ++i) {
                unsigned b = s_bits[i * 256 + tid];
                if ((b & pm) == prefix)
                    atomicAdd(&s_hist[(b >> shift) & 0xffu], 1);
            }
            __syncthreads();
            int v = s_hist[tid];
            #pragma unroll
            for (int off = 1; off < 32; off <<= 1) {
                int t2 = __shfl_down_sync(0xffffffffu, v, off);
                if (lane + off < 32) v += t2;
            }
            if (lane == 0) s_tmp[warp] = v;
            __syncthreads();
            if (tid < 8) {
                int w = s_tmp[tid];
                #pragma unroll
                for (int off = 1; off < 8; off <<= 1) {
                    int t2 = __shfl_down_sync(0xffu, w, off, 8);
                    if (tid + off < 8) w += t2;
                }
                s_tmp[8 + tid] = w;
            }
            __syncthreads();
            const int vincl = v + ((warp < 7) ? s_tmp[8 + warp + 1] : 0);
            s_suf[tid] = vincl;
            __syncthreads();
            const int suf1 = (tid < 255) ? s_suf[tid + 1] : 0;
            if (vincl >= k && suf1 < k) {
                s_sel[0] = tid;
                s_sel[1] = k - suf1;
            }
            __syncthreads();
            prefix |= ((unsigned)s_sel[0]) << shift;
            k = s_sel[1];
            __syncthreads();
        }
        const unsigned t = prefix;
        const int kfin = k;

        const int CH = IN_F / 256;
        const int base = tid * CH;
        int cnt = 0;
        #pragma unroll
        for (int j = 0; j < CH; ++j)
            if (s_bits[base + j] == t) cnt++;
        int v2 = cnt;
        #pragma unroll
        for (int off = 1; off < 32; off <<= 1) {
            int tt = __shfl_up_sync(0xffffffffu, v2, off);
            if (lane >= off) v2 += tt;
        }
        if (lane == 31) s_tmp[warp] = v2;
        __syncthreads();
        if (tid < 8) {
            int w = s_tmp[tid];
            #pragma unroll
            for (int off = 1; off < 8; off <<= 1) {
                int tt = __shfl_up_sync(0xffu, w, off, 8);
                if (tid >= off) w += tt;
            }
            s_tmp[8 + tid] = w;
        }
        __syncthreads();
        int eq_before = v2 - cnt + ((warp > 0) ? s_tmp[8 + warp - 1] : 0);

        #pragma unroll
        for (int j = 0; j < CH; ++j) {
            const int c = base + j;
            const unsigned b = s_bits[c];
            float v = 0.0f;
            if (b > t) {
                v = wrow[c];
            } else if (b == t) {
                if (eq_before < kfin) v = wrow[c];
                eq_before++;
            }
            g_wh[(size_t)row * IN_F + c] = __float2half_rn(v);
        }
        __threadfence();
        __syncthreads();
        if (tid == 0) atomicAdd(&g_mask_done[row >> 7], 1);
        return;
    }

    // ======================= GEMM tile =======================
    const int t2   = blockIdx.x - NPREP;
    const int n0 = (t2 & (N_NTILE - 1)) * BN;
    const int m0 = (t2 >> 4) * BM;

    // Wait for dependencies (writers fenced before their flag increments).
    if (tid == 0) {
        while (atomicAdd(&g_mask_done[n0 >> 7], 0) < 128) __nanosleep(64);
        while (atomicAdd(&g_a_done[m0 >> 7], 0) < 16) __nanosleep(64);
        __threadfence();
    }
    __syncthreads();

    float* s_bias = reinterpret_cast<float*>(s_bits);   // reuse static smem
    const int wid = warp;
    const int wm  = wid >> 2;            // 0..1  (64 rows each)
    const int wn  = wid & 3;             // 0..3  (32 cols each)

    const uint32_t base = (smem_u32(dsm) + 1023) & ~1023u;
    if (tid < BN) s_bias[tid] = bias[n0 + tid];

    const int lrow = lane & 15;
    const int lsel = lane >> 4;
    const uint32_t lxor_a = (uint32_t)((lane & 7) << 4);
    const int brow = (lane & 7) + ((lane >> 4) << 3);
    const int bsel = (lane >> 3) & 1;
    const uint32_t lxor_b = (uint32_t)((lane & 7) << 4);

    auto issue = [&](int kt, int st) {
        const uint32_t sa = base + st * STAGE_BYTES;
        const int k0 = kt * BK;
        #pragma unroll
        for (int i = 0; i < 4; ++i) {            // A: 128 rows x 128B (64 halves)
            const int id = i * 256 + tid;
            const int m = id >> 3, j = id & 7;
            cp16cg(sa + m * 128 + (((uint32_t)(j << 4)) ^ ((uint32_t)((m & 7) << 4))),
                   g_ah + (size_t)(m0 + m) * IN_F + k0 + j * 8);
        }
        #pragma unroll
        for (int i = 0; i < 4; ++i) {            // B: 128 rows x 128B
            const int id = i * 256 + tid;
            const int n = id >> 3, j = id & 7;
            cp16cg(sa + B_OFF + n * 128 + (((uint32_t)(j << 4)) ^ ((uint32_t)((n & 7) << 4))),
                   g_wh + (size_t)(n0 + n) * IN_F + k0 + j * 8);
        }
        asm volatile("cp.async.commit_group;\n" ::);
    };

    float acc[4][4][4] = {};

    issue(0, 0);
    issue(1, 1);

    int st = 0;
    for (int kt = 0; kt < NT; ++kt) {
        if (kt < NT - 2)
            asm volatile("cp.async.wait_group 1;\n" ::);
        else
            asm volatile("cp.async.wait_group 0;\n" ::);
        __syncthreads();

        if (kt + 2 < NT) {
            int st2 = st + 2;
            if (st2 >= NSTAGES) st2 -= NSTAGES;
            issue(kt + 2, st2);
        }

        const uint32_t sa = base + st * STAGE_BYTES;
        const uint32_t sb = sa + B_OFF;

        #pragma unroll
        for (int kk = 0; kk < 4; ++kk) {         // 4 k16 chunks in BK=64
            const uint32_t csel_a = (((uint32_t)((kk * 2 + lsel) << 4)) ^ lxor_a);
            const uint32_t csel_b = (((uint32_t)((kk * 2 + bsel) << 4)) ^ lxor_b);
            uint32_t a[4][4];
            uint32_t b[4][2];
            #pragma unroll
            for (int np = 0; np < 2; ++np) {
                uint32_t r[4];
                ldm_x4(r, sb + (uint32_t)((wn * 32 + np * 16 + brow) * 128) + csel_b);
                b[2 * np][0] = r[0]; b[2 * np][1] = r[1];
                b[2 * np + 1][0] = r[2]; b[2 * np + 1][1] = r[3];
            }
            #pragma unroll
            for (int mt = 0; mt < 4; ++mt)
                ldm_x4(a[mt], sa + (uint32_t)((wm * 64 + mt * 16 + lrow) * 128) + csel_a);
            #pragma unroll
            for (int mt = 0; mt < 4; ++mt)
                #pragma unroll
                for (int nt = 0; nt < 4; ++nt)
                    mma_f16(acc[mt][nt], a[mt], b[nt]);
        }
        ++st;
        if (st == NSTAGES) st = 0;
    }

    // Epilogue: bias add, float2 stores.
    const int g = lane >> 2;
    const int tq = lane & 3;
    #pragma unroll
    for (int mt = 0; mt < 4; ++mt) {
        const int r0 = m0 + wm * 64 + mt * 16 + g;
        #pragma unroll
        for (int nt = 0; nt < 4; ++nt) {
            const int cl = wn * 32 + nt * 8 + tq * 2;  // local col in [0,128)
            const float bx = s_bias[cl], by = s_bias[cl + 1];
            float2 o0, o1;
            o0.x = acc[mt][nt][0] + bx;
            o0.y = acc[mt][nt][1] + by;
            o1.x = acc[mt][nt][2] + bx;
            o1.y = acc[mt][nt][3] + by;
            *reinterpret_cast<float2*>(C + (size_t)r0 * OUT_F + n0 + cl) = o0;
            *reinterpret_cast<float2*>(C + (size_t)(r0 + 8) * OUT_F + n0 + cl) = o1;
        }
    }
}

// ---------------------------------------------------------------------------
extern "C" void kernel_launch(void* const* d_in, const int* in_sizes, int n_in,
                              void* d_out, int out_size) {
    const float* x    = (const float*)d_in[0];   // [M, 2048]
    const float* W    = (const float*)d_in[1];   // [2048, 2048]
    const float* bias = (const float*)d_in[2];   // [2048]
    float* out = (float*)d_out;

    const int M = in_sizes[0] / IN_F;            // 16384
    (void)M;

    cudaFuncSetAttribute(fused_kernel,
                         cudaFuncAttributeMaxDynamicSharedMemorySize, DSMEM);

    reset_kernel<<<1, 256>>>();
    const int ngemm = (OUT_F / BN) * (M_FIX / BM);   // 2048
    fused_kernel<<<NPREP + ngemm, 256, DSMEM>>>(W, (const float4*)x, bias, out);
}

// round 16
// speedup vs baseline: 1.4375x; 1.1388x over previous
#include <cuda_runtime.h>
#include <cuda_fp16.h>
#include <stdint.h>

#define IN_F   2048
#define OUT_F  2048
#define TOPK   1024
#define M_FIX  16384

#define BM 128
#define BN 128
#define BK 64
#define NSTAGES 3
#define NT (IN_F / BK)              // 32
#define STAGE_BYTES 32768           // A 16KB + B 16KB (fp16)
#define B_OFF 16384
#define DSMEM (NSTAGES * STAGE_BYTES + 1024)

// Scratch: masked W (fp16, [out][in]) and fp16 activations.
__device__ __half g_wh[(size_t)OUT_F * IN_F];
__device__ __half g_ah[(size_t)M_FIX * IN_F];

__device__ __forceinline__ uint32_t smem_u32(const void* p) {
    return (uint32_t)__cvta_generic_to_shared(p);
}
__device__ __forceinline__ void cp16cg(uint32_t dst, const void* src) {
    asm volatile("cp.async.cg.shared.global [%0], [%1], 16;\n" :: "r"(dst), "l"(src));
}
__device__ __forceinline__ void ldm_x4(uint32_t (&r)[4], uint32_t addr) {
    asm volatile("ldmatrix.sync.aligned.m8n8.x4.shared.b16 {%0,%1,%2,%3}, [%4];"
                 : "=r"(r[0]), "=r"(r[1]), "=r"(r[2]), "=r"(r[3]) : "r"(addr));
}
__device__ __forceinline__ void mma_f16(float c[4], const uint32_t a[4], const uint32_t b[2]) {
    asm volatile(
        "mma.sync.aligned.m16n8k16.row.col.f32.f16.f16.f32 "
        "{%0,%1,%2,%3}, {%4,%5,%6,%7}, {%8,%9}, {%0,%1,%2,%3};\n"
        : "+f"(c[0]), "+f"(c[1]), "+f"(c[2]), "+f"(c[3])
        : "r"(a[0]), "r"(a[1]), "r"(a[2]), "r"(a[3]), "r"(b[0]), "r"(b[1]));
}

// ---------------------------------------------------------------------------
// Kernel 1 (fused prep, parity-interleaved):
//   even blocks: per-row exact top-k mask (radix select on |w| bits, ties
//     lowest-index-first per jax.lax.top_k), row = blockIdx.x/2 -> g_wh fp16.
//     Full signed bit patterns kept in smem; |.| applied at compare time, so
//     the value write needs NO second global read of W.
//   odd blocks:  convert x slice blockIdx.x/2 to fp16 into g_ah.
// Parity interleaving keeps every scheduling wave ~50/50 mask/cvt so the
// bandwidth-heavy cvt stream overlaps the issue-bound mask stream.
// ---------------------------------------------------------------------------
__global__ void prep_kernel(const float* __restrict__ W,
                            const float4* __restrict__ x) {
    __shared__ unsigned s_bits[IN_F];      // FULL bits (sign included)
    __shared__ int s_hist[256];
    __shared__ int s_suf[256];
    __shared__ int s_tmp[16];
    __shared__ int s_sel[2];

    const int tid  = threadIdx.x;
    const int lane = tid & 31;
    const int warp = tid >> 5;

    if (blockIdx.x & 1) {
        // ---- cvt job: 4096 float4 per block ----
        const size_t base4 = (size_t)(blockIdx.x >> 1) * 4096;
        #pragma unroll
        for (int j = 0; j < 8; ++j) {
            const size_t i4 = base4 + (size_t)j * 512 + tid * 2;
            float4 v0 = x[i4];
            float4 v1 = x[i4 + 1];
            __half2 h0 = __floats2half2_rn(v0.x, v0.y);
            __half2 h1 = __floats2half2_rn(v0.z, v0.w);
            __half2 h2 = __floats2half2_rn(v1.x, v1.y);
            __half2 h3 = __floats2half2_rn(v1.z, v1.w);
            uint4 o;
            o.x = *reinterpret_cast<uint32_t*>(&h0);
            o.y = *reinterpret_cast<uint32_t*>(&h1);
            o.z = *reinterpret_cast<uint32_t*>(&h2);
            o.w = *reinterpret_cast<uint32_t*>(&h3);
            *reinterpret_cast<uint4*>(g_ah + i4 * 4) = o;
        }
        return;
    }

    // ---- mask job ----
    const int row = blockIdx.x >> 1;
    const float* wrow = W + (size_t)row * IN_F;

    // float4 load of full W bit patterns (single global read of the row).
    #pragma unroll
    for (int i = 0; i < IN_F / 1024; ++i) {
        const int c4 = i * 256 + tid;
        float4 v = reinterpret_cast<const float4*>(wrow)[c4];
        s_bits[c4 * 4 + 0] = __float_as_uint(v.x);
        s_bits[c4 * 4 + 1] = __float_as_uint(v.y);
        s_bits[c4 * 4 + 2] = __float_as_uint(v.z);
        s_bits[c4 * 4 + 3] = __float_as_uint(v.w);
    }
    __syncthreads();

    unsigned prefix = 0;
    int k = TOPK;
    #pragma unroll
    for (int pass = 0; pass < 4; ++pass) {
        const int shift = 24 - 8 * pass;
        s_hist[tid] = 0;
        __syncthreads();
        const unsigned pm = (pass == 0) ? 0u : (0xffffffffu << (shift + 8));
        #pragma unroll
        for (int i = 0; i < IN_F / 256; ++i) {
            unsigned b = s_bits[i * 256 + tid] & 0x7fffffffu;
            if ((b & pm) == prefix)
                atomicAdd(&s_hist[(b >> shift) & 0xffu], 1);
        }
        __syncthreads();
        // Inclusive SUFFIX scan of s_hist via warp shuffles.
        int v = s_hist[tid];
        #pragma unroll
        for (int off = 1; off < 32; off <<= 1) {
            int t2 = __shfl_down_sync(0xffffffffu, v, off);
            if (lane + off < 32) v += t2;
        }
        if (lane == 0) s_tmp[warp] = v;
        __syncthreads();
        if (tid < 8) {
            int w = s_tmp[tid];
            #pragma unroll
            for (int off = 1; off < 8; off <<= 1) {
                int t2 = __shfl_down_sync(0xffu, w, off, 8);
                if (tid + off < 8) w += t2;
            }
            s_tmp[8 + tid] = w;
        }
        __syncthreads();
        const int vincl = v + ((warp < 7) ? s_tmp[8 + warp + 1] : 0);
        s_suf[tid] = vincl;
        __syncthreads();
        const int suf1 = (tid < 255) ? s_suf[tid + 1] : 0;
        if (vincl >= k && suf1 < k) {
            s_sel[0] = tid;
            s_sel[1] = k - suf1;
        }
        __syncthreads();
        prefix |= ((unsigned)s_sel[0]) << shift;
        k = s_sel[1];
        __syncthreads();
    }
    const unsigned t = prefix;          // k-th largest |w| bit pattern
    const int kfin = k;                 // # of ==t to keep (lowest index first)

    // Count ==t per contiguous 8-col chunk, inclusive PREFIX scan (shuffles).
    const int CH = IN_F / 256;
    const int base = tid * CH;
    int cnt = 0;
    #pragma unroll
    for (int j = 0; j < CH; ++j)
        if ((s_bits[base + j] & 0x7fffffffu) == t) cnt++;
    int v2 = cnt;
    #pragma unroll
    for (int off = 1; off < 32; off <<= 1) {
        int tt = __shfl_up_sync(0xffffffffu, v2, off);
        if (lane >= off) v2 += tt;
    }
    if (lane == 31) s_tmp[warp] = v2;
    __syncthreads();
    if (tid < 8) {
        int w = s_tmp[tid];
        #pragma unroll
        for (int off = 1; off < 8; off <<= 1) {
            int tt = __shfl_up_sync(0xffu, w, off, 8);
            if (tid >= off) w += tt;
        }
        s_tmp[8 + tid] = w;
    }
    __syncthreads();
    int eq_before = v2 - cnt + ((warp > 0) ? s_tmp[8 + warp - 1] : 0);

    #pragma unroll
    for (int j = 0; j < CH; ++j) {
        const int c = base + j;
        const unsigned full = s_bits[c];
        const unsigned b = full & 0x7fffffffu;
        float v = 0.0f;
        if (b > t) {
            v = __uint_as_float(full);
        } else if (b == t) {
            if (eq_before < kfin) v = __uint_as_float(full);
            eq_before++;
        }
        g_wh[(size_t)row * IN_F + c] = __float2half_rn(v);
    }
}

// ---------------------------------------------------------------------------
// Kernel 2: fp16 mma.sync GEMM (f32 accumulate) — round-9/13 config,
// UNCHANGED (measured best: 311us, tensor 72.7%; crossbar/regfile-limited
// optimum of the legacy mma path — rounds 4-15 tested all neighbors).
// 128x128 tile, BK=64, 256 threads, 2x4 warps, 64x32 warp tiles,
// mma.m16n8k16, ldmatrix.x4 from XOR-swizzled smem, 3-stage cp.async ring,
// single __syncthreads per k-iter, 2 CTAs/SM.
// ---------------------------------------------------------------------------
__global__ __launch_bounds__(256, 2)
void gemm_kernel(const float* __restrict__ bias, float* __restrict__ C) {
    extern __shared__ char dsm[];
    __shared__ float s_bias[BN];

    const int tid  = threadIdx.x;
    const int lane = tid & 31;
    const int wid  = tid >> 5;
    const int wm   = wid >> 2;           // 0..1  (64 rows each)
    const int wn   = wid & 3;            // 0..3  (32 cols each)
    const int m0 = blockIdx.y * BM;
    const int n0 = blockIdx.x * BN;

    const uint32_t base = (smem_u32(dsm) + 1023) & ~1023u;
    if (tid < BN) s_bias[tid] = bias[n0 + tid];

    const int lrow = lane & 15;
    const int lsel = lane >> 4;
    const uint32_t lxor_a = (uint32_t)((lane & 7) << 4);
    const int brow = (lane & 7) + ((lane >> 4) << 3);
    const int bsel = (lane >> 3) & 1;
    const uint32_t lxor_b = (uint32_t)((lane & 7) << 4);

    auto issue = [&](int kt, int st) {
        const uint32_t sa = base + st * STAGE_BYTES;
        const int k0 = kt * BK;
        #pragma unroll
        for (int i = 0; i < 4; ++i) {            // A: 128 rows x 128B (64 halves)
            const int id = i * 256 + tid;
            const int m = id >> 3, j = id & 7;
            cp16cg(sa + m * 128 + (((uint32_t)(j << 4)) ^ ((uint32_t)((m & 7) << 4))),
                   g_ah + (size_t)(m0 + m) * IN_F + k0 + j * 8);
        }
        #pragma unroll
        for (int i = 0; i < 4; ++i) {            // B: 128 rows x 128B
            const int id = i * 256 + tid;
            const int n = id >> 3, j = id & 7;
            cp16cg(sa + B_OFF + n * 128 + (((uint32_t)(j << 4)) ^ ((uint32_t)((n & 7) << 4))),
                   g_wh + (size_t)(n0 + n) * IN_F + k0 + j * 8);
        }
        asm volatile("cp.async.commit_group;\n" ::);
    };

    float acc[4][4][4] = {};

    issue(0, 0);
    issue(1, 1);

    int st = 0;
    for (int kt = 0; kt < NT; ++kt) {
        if (kt < NT - 2)
            asm volatile("cp.async.wait_group 1;\n" ::);
        else
            asm volatile("cp.async.wait_group 0;\n" ::);
        __syncthreads();

        if (kt + 2 < NT) {
            int st2 = st + 2;
            if (st2 >= NSTAGES) st2 -= NSTAGES;
            issue(kt + 2, st2);
        }

        const uint32_t sa = base + st * STAGE_BYTES;
        const uint32_t sb = sa + B_OFF;

        #pragma unroll
        for (int kk = 0; kk < 4; ++kk) {         // 4 k16 chunks in BK=64
            const uint32_t csel_a = (((uint32_t)((kk * 2 + lsel) << 4)) ^ lxor_a);
            const uint32_t csel_b = (((uint32_t)((kk * 2 + bsel) << 4)) ^ lxor_b);
            uint32_t a[4][4];
            uint32_t b[4][2];
            #pragma unroll
            for (int np = 0; np < 2; ++np) {
                uint32_t r[4];
                ldm_x4(r, sb + (uint32_t)((wn * 32 + np * 16 + brow) * 128) + csel_b);
                b[2 * np][0] = r[0]; b[2 * np][1] = r[1];
                b[2 * np + 1][0] = r[2]; b[2 * np + 1][1] = r[3];
            }
            #pragma unroll
            for (int mt = 0; mt < 4; ++mt)
                ldm_x4(a[mt], sa + (uint32_t)((wm * 64 + mt * 16 + lrow) * 128) + csel_a);
            #pragma unroll
            for (int mt = 0; mt < 4; ++mt)
                #pragma unroll
                for (int nt = 0; nt < 4; ++nt)
                    mma_f16(acc[mt][nt], a[mt], b[nt]);
        }
        ++st;
        if (st == NSTAGES) st = 0;
    }

    // Epilogue: bias add, float2 stores.
    const int g = lane >> 2;
    const int t = lane & 3;
    #pragma unroll
    for (int mt = 0; mt < 4; ++mt) {
        const int r0 = m0 + wm * 64 + mt * 16 + g;
        #pragma unroll
        for (int nt = 0; nt < 4; ++nt) {
            const int cl = wn * 32 + nt * 8 + t * 2;   // local col in [0,128)
            const float bx = s_bias[cl], by = s_bias[cl + 1];
            float2 o0, o1;
            o0.x = acc[mt][nt][0] + bx;
            o0.y = acc[mt][nt][1] + by;
            o1.x = acc[mt][nt][2] + bx;
            o1.y = acc[mt][nt][3] + by;
            *reinterpret_cast<float2*>(C + (size_t)r0 * OUT_F + n0 + cl) = o0;
            *reinterpret_cast<float2*>(C + (size_t)(r0 + 8) * OUT_F + n0 + cl) = o1;
        }
    }
}

// ---------------------------------------------------------------------------
extern "C" void kernel_launch(void* const* d_in, const int* in_sizes, int n_in,
                              void* d_out, int out_size) {
    const float* x    = (const float*)d_in[0];   // [M, 2048]
    const float* W    = (const float*)d_in[1];   // [2048, 2048]
    const float* bias = (const float*)d_in[2];   // [2048]
    float* out = (float*)d_out;

    const int M = in_sizes[0] / IN_F;            // 16384

    cudaFuncSetAttribute(gemm_kernel,
                         cudaFuncAttributeMaxDynamicSharedMemorySize, DSMEM);

    // Fused prep, parity-interleaved: 2048 mask + 2048 cvt blocks.
    const int cvt_blocks = (M * (IN_F / 4)) / 4096;  // 2048
    prep_kernel<<<OUT_F + cvt_blocks, 256>>>(W, (const float4*)x);

    dim3 grid(OUT_F / BN, M / BM);               // (16, 128)
    gemm_kernel<<<grid, 256, DSMEM>>>(bias, out);
}